// round 4
// baseline (speedup 1.0000x reference)
#include <cuda_runtime.h>

// ---------------- problem constants ----------------
#define Bc   64
#define Tc   1024
#define Dc   1024
#define NB   128      // persistent blocks (<= 148 SMs, 1 block/SM)
#define NT   256      // threads per block (8 warps, 2 per SMSP)
#define KT   32       // k-tile
#define PAD  36       // smem row pitch in floats (= 9 x 16B, conflict-free)
#define DPB  8        // d-columns owned per block (1024/128)
#define NKT  64       // 2048 / KT

// ---------------- persistent device state ----------------
__device__ __align__(256) float g_h0[2][Bc * Dc];
__device__ __align__(256) float g_h1[2][Bc * Dc];
__device__ __align__(256) float g_c0[Bc * Dc];
__device__ __align__(256) float g_c1[Bc * Dc];
__device__ unsigned g_bar_count = 0;
__device__ unsigned g_bar_gen   = 0;

// ---------------- small helpers ----------------
__device__ __forceinline__ void cpa16(unsigned dst, const void* src) {
    asm volatile("cp.async.cg.shared.global [%0], [%1], 16;" :: "r"(dst), "l"(src));
}
#define CP_COMMIT() asm volatile("cp.async.commit_group;")

// packed fp32x2 FMA: d += a*b on both lanes (PTX-only path on sm_103a)
#define FMA2(d, a, b) \
    asm("fma.rn.f32x2 %0, %1, %2, %0;" : "+l"(d) : "l"(a), "l"(b))

__device__ __forceinline__ float sigf(float x) {
    return 1.0f / (1.0f + __expf(-x));
}

// Self-resetting grid barrier (monotonic generation counter: safe across
// CUDA-graph replays; g_bar_count returns to 0 after every barrier).
__device__ __forceinline__ void grid_barrier() {
    __threadfence();            // make this block's global writes visible (L2)
    __syncthreads();
    if (threadIdx.x == 0) {
        unsigned gen = atomicAdd(&g_bar_gen, 0u);
        if (atomicAdd(&g_bar_count, 1u) == NB - 1) {
            atomicExch(&g_bar_count, 0u);
            __threadfence();
            atomicAdd(&g_bar_gen, 1u);
        } else {
            while (atomicAdd(&g_bar_gen, 0u) == gen) { __nanosleep(64); }
        }
    }
    __syncthreads();
}

// ---------------- tile prefetch (cp.async, L2-direct) ----------------
// A tile: [64 rows(batch) x KT k] ; W tile: [32 gate-cols x KT k]
// K = 2048 = [0,1024): (x or h0_new) with Wih ; [1024,2048): h_prev with Whh
__device__ __forceinline__ void load_tile(
    int kt, int buf,
    const float* __restrict__ Alo, long strideLo,
    const float* __restrict__ Ahi,
    const float* __restrict__ Wih, const float* __restrict__ Whh,
    int d0,
    float (&sA)[2][64 * PAD], float (&sW)[2][32 * PAD])
{
    const int k0 = kt * KT;
    const float* Asrc; long astr; const float* Wsrc; int kl;
    if (k0 < Dc) { Asrc = Alo; astr = strideLo; Wsrc = Wih; kl = k0; }
    else         { Asrc = Ahi; astr = Dc;       Wsrc = Whh; kl = k0 - Dc; }

    unsigned aB = (unsigned)__cvta_generic_to_shared(&sA[buf][0]);
    unsigned wB = (unsigned)__cvta_generic_to_shared(&sW[buf][0]);
    const int tid = threadIdx.x;

    // A: 64 rows x 32 floats = 512 x 16B chunks  (2 per thread)
#pragma unroll
    for (int i = 0; i < 2; i++) {
        int idx = tid + i * NT;
        int row = idx >> 3, kq = idx & 7;
        cpa16(aB + (unsigned)(row * PAD + kq * 4) * 4u,
              Asrc + (long)row * astr + kl + kq * 4);
    }
    // W: 32 cols x 32 floats = 256 x 16B chunks  (1 per thread). col = gate*8 + dd
    {
        int idx = tid;
        int col = idx >> 3, kq = idx & 7;
        int wr  = (col >> 3) * Dc + d0 + (col & 7);   // global gate row
        cpa16(wB + (unsigned)(col * PAD + kq * 4) * 4u,
              Wsrc + (long)wr * Dc + kl + kq * 4);
    }
    CP_COMMIT();
}

// ---------------- one LSTM cell step for this block's d-slice ----------------
// Computes gates[64 x 32cols] = [Alo|Ahi] @ W^T rows, then the cell update.
// Thread (tx=tid&7, ty=tid>>3, ty in [0,32)): rows {32r+ty}, cols {8c+tx}
//   -> gate c of d=d0+tx
__device__ __forceinline__ void do_layer(
    const float* __restrict__ Alo, long strideLo,
    const float* __restrict__ Ahi,
    const float* __restrict__ Wih, const float* __restrict__ Whh,
    float* __restrict__ cst, float* __restrict__ hnext,
    float* __restrict__ outp,            // null for layer0, out + t*D for layer1
    int d0,
    float (&sA)[2][64 * PAD], float (&sW)[2][32 * PAD])
{
    const int tid = threadIdx.x;
    const int tx = tid & 7;        // -> d offset (dd)
    const int ty = tid >> 3;       // -> batch row (0..31)

    // f32x2 accumulators: lane0 = even-k partial, lane1 = odd-k partial
    unsigned long long acc[2][4];
#pragma unroll
    for (int r = 0; r < 2; r++)
#pragma unroll
        for (int c = 0; c < 4; c++) acc[r][c] = 0ull;

    load_tile(0, 0, Alo, strideLo, Ahi, Wih, Whh, d0, sA, sW);

    for (int kt = 0; kt < NKT; kt++) {
        if (kt < NKT - 1) {
            load_tile(kt + 1, (kt + 1) & 1, Alo, strideLo, Ahi, Wih, Whh, d0, sA, sW);
            asm volatile("cp.async.wait_group 1;");
        } else {
            asm volatile("cp.async.wait_group 0;");
        }
        __syncthreads();

        const float* A = sA[kt & 1];
        const float* W = sW[kt & 1];
#pragma unroll
        for (int kk = 0; kk < KT; kk += 4) {
            ulonglong2 av[2], wv[4];
#pragma unroll
            for (int r = 0; r < 2; r++)
                av[r] = *reinterpret_cast<const ulonglong2*>(&A[(32 * r + ty) * PAD + kk]);
#pragma unroll
            for (int c = 0; c < 4; c++)
                wv[c] = *reinterpret_cast<const ulonglong2*>(&W[(8 * c + tx) * PAD + kk]);
#pragma unroll
            for (int r = 0; r < 2; r++)
#pragma unroll
                for (int c = 0; c < 4; c++) {
                    FMA2(acc[r][c], av[r].x, wv[c].x);
                    FMA2(acc[r][c], av[r].y, wv[c].y);
                }
        }
        __syncthreads();
    }

    // cell update: thread owns all 4 gates for d = d0+tx, b = 32r+ty
    const int dglob = d0 + tx;
#pragma unroll
    for (int r = 0; r < 2; r++) {
        float2 v;
        v = *reinterpret_cast<float2*>(&acc[r][0]); float gi = v.x + v.y;
        v = *reinterpret_cast<float2*>(&acc[r][1]); float gf = v.x + v.y;
        v = *reinterpret_cast<float2*>(&acc[r][2]); float gg = v.x + v.y;
        v = *reinterpret_cast<float2*>(&acc[r][3]); float go = v.x + v.y;

        float ii = sigf(gi);
        float ff = sigf(gf);
        float gv = tanhf(gg);
        float oo = sigf(go);

        const int  b  = 32 * r + ty;
        const long si = (long)b * Dc + dglob;
        float cn = ff * cst[si] + ii * gv;
        cst[si] = cn;
        float hn = oo * tanhf(cn);
        hnext[si] = hn;
        if (outp) outp[(long)b * Tc * Dc + dglob] = hn;
    }
}

// ---------------- persistent kernel ----------------
__global__ void __launch_bounds__(NT, 1)
lstm_persistent(const float* __restrict__ x,
                const float* __restrict__ Wih0, const float* __restrict__ Whh0,
                const float* __restrict__ Wih1, const float* __restrict__ Whh1,
                float* __restrict__ out)
{
    __shared__ __align__(16) float sA[2][64 * PAD];
    __shared__ __align__(16) float sW[2][32 * PAD];

    const int d0  = blockIdx.x * DPB;
    const int tid = threadIdx.x;

    // zero initial state (phase-0 h buffers + c) for this block's d slice
    for (int j = tid; j < Bc * DPB; j += NT) {
        int b = j & 63, dd = j >> 6;
        long si = (long)b * Dc + d0 + dd;
        g_h0[0][si] = 0.0f;
        g_h1[0][si] = 0.0f;
        g_c0[si]    = 0.0f;
        g_c1[si]    = 0.0f;
    }
    grid_barrier();

    for (int t = 0; t < Tc; t++) {
        const int p = t & 1;
        // layer 0: gates = x_t @ Wih0^T + h0_prev @ Whh0^T
        do_layer(x + (long)t * Dc, (long)Tc * Dc, g_h0[p],
                 Wih0, Whh0, g_c0, g_h0[p ^ 1], (float*)0, d0, sA, sW);
        grid_barrier();
        // layer 1: gates = h0_new @ Wih1^T + h1_prev @ Whh1^T ; h1 -> out
        do_layer(g_h0[p ^ 1], (long)Dc, g_h1[p],
                 Wih1, Whh1, g_c1, g_h1[p ^ 1], out + (long)t * Dc, d0, sA, sW);
        grid_barrier();
    }
}

// ---------------- harness entry ----------------
extern "C" void kernel_launch(void* const* d_in, const int* in_sizes, int n_in,
                              void* d_out, int out_size)
{
    const float* x    = (const float*)d_in[0];
    const float* Wih0 = (const float*)d_in[1];
    const float* Whh0 = (const float*)d_in[2];
    const float* Wih1 = (const float*)d_in[3];
    const float* Whh1 = (const float*)d_in[4];
    float* out        = (float*)d_out;
    (void)in_sizes; (void)n_in; (void)out_size;

    lstm_persistent<<<NB, NT>>>(x, Wih0, Whh0, Wih1, Whh1, out);
}

// round 16
// speedup vs baseline: 2.3435x; 2.3435x over previous
#include <cuda_runtime.h>
#include <cuda_bf16.h>
#include <cstdint>
#include <cstddef>

// ---------------- constants ----------------
#define Bc 64
#define Tc 1024
#define Dc 1024
#define NB 128
#define NT 256

#define PITCH 72                  // bf16 elems per smem tile row (9 x 16B: conflict-free)
#define STG_A_HI 0
#define STG_A_LO (64 * PITCH)
#define STG_W_HI (128 * PITCH)
#define STG_W_LO (160 * PITCH)
#define STG_ELEMS (192 * PITCH)   // 13824 bf16 = 27648 B per stage
#define NSTG 3
#define GPITCH 36
#define SMEM_BYTES (NSTG * STG_ELEMS * 2 + 64 * GPITCH * 4)   // 82944 + 9216 = 92160

// ---------------- persistent device state ----------------
__device__ __align__(1024) __nv_bfloat16 g_xh[(size_t)Tc * Bc * Dc];   // [t][b][d]
__device__ __align__(1024) __nv_bfloat16 g_xl[(size_t)Tc * Bc * Dc];
__device__ __align__(1024) __nv_bfloat16 g_Wh[2][(size_t)4096 * 2048]; // packed rows
__device__ __align__(1024) __nv_bfloat16 g_Wl[2][(size_t)4096 * 2048];
__device__ __align__(1024) __nv_bfloat16 g_h0h[2][Bc * Dc];
__device__ __align__(1024) __nv_bfloat16 g_h0l[2][Bc * Dc];
__device__ __align__(1024) __nv_bfloat16 g_h1h[2][Bc * Dc];
__device__ __align__(1024) __nv_bfloat16 g_h1l[2][Bc * Dc];
__device__ float g_c0[Bc * Dc];
__device__ float g_c1[Bc * Dc];
__device__ unsigned g_bar_count = 0;
__device__ unsigned g_bar_gen   = 0;

// ---------------- helpers ----------------
__device__ __forceinline__ uint32_t smem_u32(const void* p) {
    uint32_t a;
    asm("{ .reg .u64 t; cvta.to.shared.u64 t, %1; cvt.u32.u64 %0, t; }" : "=r"(a) : "l"(p));
    return a;
}
__device__ __forceinline__ void cpa16(uint32_t dst, const void* src) {
    asm volatile("cp.async.cg.shared.global [%0], [%1], 16;" :: "r"(dst), "l"(src));
}
__device__ __forceinline__ void ldsm4(uint32_t* r, uint32_t addr) {
    asm volatile("ldmatrix.sync.aligned.m8n8.x4.shared.b16 {%0,%1,%2,%3}, [%4];"
        : "=r"(r[0]), "=r"(r[1]), "=r"(r[2]), "=r"(r[3]) : "r"(addr));
}
__device__ __forceinline__ void mma_bf16(float* d, const uint32_t* a, uint32_t b0, uint32_t b1) {
    asm volatile("mma.sync.aligned.m16n8k16.row.col.f32.bf16.bf16.f32 "
        "{%0,%1,%2,%3}, {%4,%5,%6,%7}, {%8,%9}, {%0,%1,%2,%3};"
        : "+f"(d[0]), "+f"(d[1]), "+f"(d[2]), "+f"(d[3])
        : "r"(a[0]), "r"(a[1]), "r"(a[2]), "r"(a[3]), "r"(b0), "r"(b1));
}
__device__ __forceinline__ float sigf(float x) { return 1.0f / (1.0f + __expf(-x)); }
__device__ __forceinline__ void bf16split(float v, __nv_bfloat16& h, __nv_bfloat16& l) {
    h = __float2bfloat16(v);
    l = __float2bfloat16(v - __bfloat162float(h));
}
__device__ __forceinline__ void grid_barrier() {
    __threadfence();
    __syncthreads();
    if (threadIdx.x == 0) {
        unsigned gen = atomicAdd(&g_bar_gen, 0u);
        if (atomicAdd(&g_bar_count, 1u) == NB - 1) {
            atomicExch(&g_bar_count, 0u);
            __threadfence();
            atomicAdd(&g_bar_gen, 1u);
        } else {
            while (atomicAdd(&g_bar_gen, 0u) == gen) { __nanosleep(64); }
        }
    }
    __syncthreads();
}

// ---------------- setup: split x, pack+split W, zero state ----------------
__global__ void lstm_setup(const float* __restrict__ x,
                           const float* __restrict__ Wih0, const float* __restrict__ Whh0,
                           const float* __restrict__ Wih1, const float* __restrict__ Whh1)
{
    const size_t stride = (size_t)gridDim.x * blockDim.x;
    const size_t t0 = (size_t)blockIdx.x * blockDim.x + threadIdx.x;

    const size_t NX = (size_t)Tc * Bc * Dc;
    for (size_t i = t0; i < NX; i += stride) {
        size_t t = i >> 16, b = (i >> 10) & 63, d = i & 1023;
        float v = x[b * (size_t)(Tc * Dc) + t * Dc + d];
        __nv_bfloat16 h, l; bf16split(v, h, l);
        g_xh[i] = h; g_xl[i] = l;
    }
    // packed weights: row n = bi*32 + gate*8 + dd, k in [0,2048)
    const size_t NW = (size_t)2 * 4096 * 2048;
    for (size_t i = t0; i < NW; i += stride) {
        int L = (int)(i >> 23);
        int n = (int)((i >> 11) & 4095);
        int k = (int)(i & 2047);
        int bi = n >> 5, c = n & 31, g = c >> 3, dd = c & 7;
        int row = g * 1024 + bi * 8 + dd;
        const float* W = L ? (k < 1024 ? Wih1 : Whh1) : (k < 1024 ? Wih0 : Whh0);
        float v = W[(size_t)row * 1024 + (k & 1023)];
        __nv_bfloat16 h, l; bf16split(v, h, l);
        g_Wh[L][(size_t)n * 2048 + k] = h;
        g_Wl[L][(size_t)n * 2048 + k] = l;
    }
    __nv_bfloat16 z = __float2bfloat16(0.0f);
    for (size_t i = t0; i < (size_t)Bc * Dc; i += stride) {
        g_h0h[0][i] = z; g_h0l[0][i] = z;
        g_h1h[0][i] = z; g_h1l[0][i] = z;
        g_c0[i] = 0.0f; g_c1[i] = 0.0f;
    }
}

// ---------------- stage prefetch (all 256 threads) ----------------
__device__ __forceinline__ void issue_stage(
    int s, int tid, uint32_t sbase, int n0,
    const __nv_bfloat16* loH, const __nv_bfloat16* loL,
    const __nv_bfloat16* hiH, const __nv_bfloat16* hiL,
    const __nv_bfloat16* Wh_, const __nv_bfloat16* Wl_)
{
    const int k0 = s * 64;
    const __nv_bfloat16 *aH, *aL; int koff;
    if (k0 < 1024) { aH = loH; aL = loL; koff = k0; }
    else           { aH = hiH; aL = hiL; koff = k0 - 1024; }
    const uint32_t st = sbase + (uint32_t)(s % NSTG) * (STG_ELEMS * 2);

#pragma unroll
    for (int i = 0; i < 6; i++) {
        const int id = tid + i * NT;
        if (id < 1024) {                    // A tiles (hi: 0-511, lo: 512-1023)
            const int rid = id & 511;
            const int row = rid >> 3, kq = rid & 7;
            const __nv_bfloat16* src = (id < 512 ? aH : aL) + (size_t)row * 1024 + koff + kq * 8;
            const uint32_t dst = st + (uint32_t)((id < 512 ? STG_A_HI : STG_A_LO) + row * PITCH + kq * 8) * 2u;
            cpa16(dst, src);
        } else {                            // W tiles (hi: 1024-1279, lo: 1280-1535)
            const int rid = (id - 1024) & 255;
            const int row = rid >> 3, kq = rid & 7;
            const __nv_bfloat16* src = (id < 1280 ? Wh_ : Wl_) + (size_t)(n0 + row) * 2048 + k0 + kq * 8;
            const uint32_t dst = st + (uint32_t)((id < 1280 ? STG_W_HI : STG_W_LO) + row * PITCH + kq * 8) * 2u;
            cpa16(dst, src);
        }
    }
    asm volatile("cp.async.commit_group;");
}

// ---------------- main persistent kernel ----------------
__global__ void __launch_bounds__(NT, 1)
lstm_hmma(float* __restrict__ out)
{
    extern __shared__ __align__(16) char smem[];
    __nv_bfloat16* sT = (__nv_bfloat16*)smem;
    float* sG = (float*)(smem + NSTG * STG_ELEMS * 2);
    const uint32_t sbase = smem_u32(sT);

    const int tid = threadIdx.x;
    const int wid = tid >> 5;
    const int lane = tid & 31;
    const int wm = wid >> 1;          // 0..3 -> batch rows 16*wm
    const int wn = wid & 1;           // 0..1 -> gate cols 16*wn
    const int bi = blockIdx.x;
    const int n0 = bi * 32;           // packed W row origin
    const int d0g = bi * 8;           // d-slice origin

    // per-lane ldmatrix address offsets (within a stage)
    const int lrow = (lane & 7) + ((lane >> 3) & 1) * 8;
    const int lk   = ((lane >> 4) & 1) * 8;
    const uint32_t aHiOff = (uint32_t)(STG_A_HI + (16 * wm + lrow) * PITCH + lk) * 2u;
    const uint32_t aLoOff = (uint32_t)(STG_A_LO + (16 * wm + lrow) * PITCH + lk) * 2u;
    const uint32_t wHiOff = (uint32_t)(STG_W_HI + (16 * wn + lrow) * PITCH + lk) * 2u;
    const uint32_t wLoOff = (uint32_t)(STG_W_LO + (16 * wn + lrow) * PITCH + lk) * 2u;

    for (int t = 0; t < Tc; t++) {
        const int p = t & 1, q = p ^ 1;
        for (int L = 0; L < 2; L++) {
            const __nv_bfloat16 *loH, *loL, *hiH, *hiL, *Wh_, *Wl_;
            if (L == 0) {
                loH = g_xh + (size_t)t * (Bc * Dc);
                loL = g_xl + (size_t)t * (Bc * Dc);
                hiH = g_h0h[p]; hiL = g_h0l[p];
                Wh_ = g_Wh[0]; Wl_ = g_Wl[0];
            } else {
                loH = g_h0h[q]; loL = g_h0l[q];
                hiH = g_h1h[p]; hiL = g_h1l[p];
                Wh_ = g_Wh[1]; Wl_ = g_Wl[1];
            }

            float d0[4] = {0.f, 0.f, 0.f, 0.f};   // n-tile 0 (cols 16wn+0..7)
            float d1[4] = {0.f, 0.f, 0.f, 0.f};   // n-tile 1 (cols 16wn+8..15)

            issue_stage(0, tid, sbase, n0, loH, loL, hiH, hiL, Wh_, Wl_);
            issue_stage(1, tid, sbase, n0, loH, loL, hiH, hiL, Wh_, Wl_);
            issue_stage(2, tid, sbase, n0, loH, loL, hiH, hiL, Wh_, Wl_);

            for (int s = 0; s < 32; s++) {
                // Drain schedule: ensure stage s is complete. After issues stop
                // (last issue = stage 31 at s==28), the "2 newest pending" no
                // longer excludes stage s itself — tighten the wait.
                if (s < 30)       asm volatile("cp.async.wait_group 2;");
                else if (s == 30) asm volatile("cp.async.wait_group 1;");
                else              asm volatile("cp.async.wait_group 0;");
                __syncthreads();
                const uint32_t stb = sbase + (uint32_t)(s % NSTG) * (STG_ELEMS * 2);
#pragma unroll
                for (int kk = 0; kk < 64; kk += 16) {
                    uint32_t ah[4], al[4], wh[4], wl[4];
                    ldsm4(ah, stb + aHiOff + kk * 2);
                    ldsm4(al, stb + aLoOff + kk * 2);
                    ldsm4(wh, stb + wHiOff + kk * 2);
                    ldsm4(wl, stb + wLoOff + kk * 2);
                    mma_bf16(d0, ah, wh[0], wh[2]);
                    mma_bf16(d1, ah, wh[1], wh[3]);
                    mma_bf16(d0, ah, wl[0], wl[2]);
                    mma_bf16(d1, ah, wl[1], wl[3]);
                    mma_bf16(d0, al, wh[0], wh[2]);
                    mma_bf16(d1, al, wh[1], wh[3]);
                }
                __syncthreads();
                if (s + 3 < 32)
                    issue_stage(s + 3, tid, sbase, n0, loH, loL, hiH, hiL, Wh_, Wl_);
            }

            // ---- epilogue: D -> smem gates ----
            {
                const int r0 = 16 * wm + (lane >> 2);
                const int c0 = 16 * wn + 2 * (lane & 3);
                sG[r0 * GPITCH + c0]           = d0[0];
                sG[r0 * GPITCH + c0 + 1]       = d0[1];
                sG[(r0 + 8) * GPITCH + c0]     = d0[2];
                sG[(r0 + 8) * GPITCH + c0 + 1] = d0[3];
                sG[r0 * GPITCH + c0 + 8]           = d1[0];
                sG[r0 * GPITCH + c0 + 9]           = d1[1];
                sG[(r0 + 8) * GPITCH + c0 + 8]     = d1[2];
                sG[(r0 + 8) * GPITCH + c0 + 9]     = d1[3];
            }
            __syncthreads();

            // ---- cell update: 2 (b,d) pairs per thread ----
            float* cst = L ? g_c1 : g_c0;
            __nv_bfloat16* hh = L ? g_h1h[q] : g_h0h[q];
            __nv_bfloat16* hl = L ? g_h1l[q] : g_h0l[q];
#pragma unroll
            for (int ii = 0; ii < 2; ii++) {
                const int idx = tid + ii * NT;      // 0..511
                const int b = idx >> 3, dd = idx & 7;
                const float gi = sG[b * GPITCH + dd];
                const float gf = sG[b * GPITCH + 8 + dd];
                const float gg = sG[b * GPITCH + 16 + dd];
                const float go = sG[b * GPITCH + 24 + dd];
                const float iv = sigf(gi), fv = sigf(gf);
                const float gv = tanhf(gg), ov = sigf(go);
                const int d = d0g + dd;
                const long si = (long)b * Dc + d;
                const float cn = fv * cst[si] + iv * gv;
                cst[si] = cn;
                const float hn = ov * tanhf(cn);
                __nv_bfloat16 h_, l_; bf16split(hn, h_, l_);
                hh[si] = h_; hl[si] = l_;
                if (L) out[(long)b * (Tc * Dc) + (long)t * Dc + d] = hn;
            }

            grid_barrier();
        }
    }
}

// ---------------- harness entry ----------------
extern "C" void kernel_launch(void* const* d_in, const int* in_sizes, int n_in,
                              void* d_out, int out_size)
{
    const float* x    = (const float*)d_in[0];
    const float* Wih0 = (const float*)d_in[1];
    const float* Whh0 = (const float*)d_in[2];
    const float* Wih1 = (const float*)d_in[3];
    const float* Whh1 = (const float*)d_in[4];
    float* out        = (float*)d_out;
    (void)in_sizes; (void)n_in; (void)out_size;

    cudaFuncSetAttribute(lstm_hmma, cudaFuncAttributeMaxDynamicSharedMemorySize, SMEM_BYTES);

    lstm_setup<<<1024, 256>>>(x, Wih0, Whh0, Wih1, Whh1);
    lstm_hmma<<<NB, NT, SMEM_BYTES>>>(out);
}